// round 15
// baseline (speedup 1.0000x reference)
#include <cuda_runtime.h>
#include <math.h>
#include <stdint.h>

#define BB   32
#define TT   512
#define HH   256
#define CC   32
#define G4   1024   // 4*H
#define DD   256

typedef unsigned long long ull;

// ---------------- scratch (no allocations allowed) ----------------
// gx layout: [dir][t][b][col]  (col fastest, 1024 per dir)
__device__ float g_gx[(size_t)2 * TT * BB * G4];     // 134 MB
__device__ float g_hist[(size_t)2 * TT * HH * BB];   // [dir][t][n][b]  33 MB
__device__ float g_logits[(size_t)TT * BB * CC];     // [t][b][c]        2 MB
// h exchange slabs per group: [16][parity][256 cols][4 b] duplicated ull
__device__ ull   g_hx[16 * 2048];                    // 256 KB
__device__ int   g_ctr[16 * 32];                     // 1 counter per group, 128B apart

// ---------------- packed fp32x2 helpers ----------------
__device__ __forceinline__ ull ffma2(ull a, ull b, ull c) {
    ull d;
    asm("fma.rn.f32x2 %0, %1, %2, %3;" : "=l"(d) : "l"(a), "l"(b), "l"(c));
    return d;
}
__device__ __forceinline__ ull padd2(ull a, ull b) {
    ull d;
    asm("add.rn.f32x2 %0, %1, %2;" : "=l"(d) : "l"(a), "l"(b));
    return d;
}
__device__ __forceinline__ ull dup2(float x) {
    ull p = (ull)__float_as_uint(x);
    return p | (p << 32);
}
__device__ __forceinline__ float2 unp(ull v) {
    float2 f;
    asm("mov.b64 {%0, %1}, %2;" : "=f"(f.x), "=f"(f.y) : "l"(v));
    return f;
}

__device__ __forceinline__ float sigf(float x)  { return __fdividef(1.f, 1.f + __expf(-x)); }
__device__ __forceinline__ float tanhf_(float x){ return __fdividef(2.f, 1.f + __expf(-2.f * x)) - 1.f; }

// release-add / acquire-load pair
__device__ __forceinline__ void red_release_add(int* p, int v) {
    asm volatile("red.release.gpu.global.add.s32 [%0], %1;" :: "l"(p), "r"(v) : "memory");
}
__device__ __forceinline__ int ld_acquire(const int* p) {
    int v;
    asm volatile("ld.acquire.gpu.global.b32 %0, [%1];" : "=r"(v) : "l"(p) : "memory");
    return v;
}

// ---------------- init: zero counters each replay ----------------
__global__ void init_kernel() {
    int i = blockIdx.x * blockDim.x + threadIdx.x;
    if (i < 16 * 32) g_ctr[i] = 0;
}

// ---------------- kernel A: embedding gather + x@Wi + bias (fp32x2) ----------------
// grid (512, 16): x = t, y = dir*8 + colblock(128 cols). 256 threads.
__global__ void __launch_bounds__(256) wi_gemm_kernel(
        const int* __restrict__ chars,
        const int* __restrict__ bigrams,
        const float* __restrict__ char_table,
        const float* __restrict__ bigram_table,
        const float* __restrict__ Wi_f,
        const float* __restrict__ bias_f,
        const float* __restrict__ Wi_b,
        const float* __restrict__ bias_b) {
    extern __shared__ float sm[];
    float* a_sm = sm;                       // 8192 floats = 32KB
    ull*   wd_sm = (ull*)(sm + 8192);       // 8192 ull = 64KB

    const int t   = blockIdx.x;
    const int yid = blockIdx.y;
    const int dir = yid >> 3;
    const int cb  = yid & 7;
    const float* Wi   = dir ? Wi_b  : Wi_f;
    const float* bias = dir ? bias_b : bias_f;

    const int tid = threadIdx.x;

    // gather emb -> a_sm[k][b]
    {
        const int b    = tid & 31;
        const int part = tid >> 5;
        const int ci = chars[b * TT + t];
        const int bi = bigrams[b * TT + t];
        #pragma unroll
        for (int i = 0; i < 8; i++) {
            int k4 = part * 8 + i;
            float4 v;
            if (k4 < 32) v = ((const float4*)char_table)[(size_t)ci * 32 + k4];
            else         v = ((const float4*)bigram_table)[(size_t)bi * 32 + (k4 - 32)];
            a_sm[(k4 * 4 + 0) * 32 + b] = v.x;
            a_sm[(k4 * 4 + 1) * 32 + b] = v.y;
            a_sm[(k4 * 4 + 2) * 32 + b] = v.z;
            a_sm[(k4 * 4 + 3) * 32 + b] = v.w;
        }
    }

    const int cg = tid >> 3;   // cols cg*4 .. cg*4+3
    const int bq = tid & 7;    // batches 4bq .. 4bq+3
    ull acc[8];
    #pragma unroll
    for (int i = 0; i < 8; i++) acc[i] = 0ull;

    const ulonglong2* a2 = (const ulonglong2*)a_sm;

    for (int ch = 0; ch < 4; ch++) {
        const int k0 = ch * 64;
        __syncthreads();
        for (int u = tid; u < 8192; u += 256) {
            int kk  = u >> 7;
            int col = u & 127;
            float wv = Wi[(size_t)(k0 + kk) * G4 + cb * 128 + col];
            wd_sm[u] = dup2(wv);
        }
        __syncthreads();
        #pragma unroll 8
        for (int kk = 0; kk < 64; kk++) {
            ulonglong2 hv = a2[(k0 + kk) * 8 + bq];
            const ull* wr = &wd_sm[kk * 128 + cg * 4];
            #pragma unroll
            for (int c = 0; c < 4; c++) {
                ull wd = wr[c];
                acc[2 * c]     = ffma2(hv.x, wd, acc[2 * c]);
                acc[2 * c + 1] = ffma2(hv.y, wd, acc[2 * c + 1]);
            }
        }
    }

    // transpose in smem, then store as [dir][t][b][col]
    __syncthreads();
    {
        #pragma unroll
        for (int cc = 0; cc < 4; cc++) {
            int col = cg * 4 + cc;
            ull b2 = dup2(bias[cb * 128 + col]);
            float2 v01 = unp(padd2(acc[2 * cc],     b2));
            float2 v23 = unp(padd2(acc[2 * cc + 1], b2));
            a_sm[(bq * 4 + 0) * 129 + col] = v01.x;
            a_sm[(bq * 4 + 1) * 129 + col] = v01.y;
            a_sm[(bq * 4 + 2) * 129 + col] = v23.x;
            a_sm[(bq * 4 + 3) * 129 + col] = v23.y;
        }
    }
    __syncthreads();
    {
        float* outp = g_gx + (size_t)(dir * TT + t) * (32 * 1024) + cb * 128;
        #pragma unroll
        for (int i = 0; i < 4; i++) {
            int idx = tid + i * 256;
            int b = idx >> 5, c4 = idx & 31;
            float4 v;
            v.x = a_sm[b * 129 + c4 * 4 + 0];
            v.y = a_sm[b * 129 + c4 * 4 + 1];
            v.z = a_sm[b * 129 + c4 * 4 + 2];
            v.w = a_sm[b * 129 + c4 * 4 + 3];
            *(float4*)(outp + (size_t)b * 1024 + c4 * 4) = v;
        }
    }
}

// ---------------- kernel B: recurrent scan, dual-group interleave ----------------
// grid 64 CTAs of 128 threads: CTA = (dir, bgp in 0..3, cg in 0..7).
// Each CTA runs TWO groups: A=(dir,bgp) and B=(dir,bgp+4) — same Wh slice.
// Group A's exchange latency is hidden under group B's compute and vice versa.
__global__ void __launch_bounds__(128, 1)
scan_kernel(const float* __restrict__ Wh_f,
            const float* __restrict__ Wh_b,
            const int* __restrict__ seq_len) {
    extern __shared__ float sm[];
    float*      sm_wh   = sm;                             // [256][128] f32 = 128KB
    ull*        sm_hdA  = (ull*)(sm + 32768);             // [256][4] dup ull = 8KB
    ull*        sm_hdB  = sm_hdA + 1024;                  // 8KB
    float*      sm_g    = (float*)(sm_hdB + 1024);        // [2][4 b][128 l] = 4KB (shared A/B)
    ulonglong2* sm_part = (ulonglong2*)(sm_g + 1024);     // [3][32][4] u2 = 6KB (shared A/B)
    float*      sm_hoA  = (float*)(sm_part + 3 * 32 * 4); // [2][32][4] = 1KB
    float*      sm_hoB  = sm_hoA + 256;                   // 1KB

    const int cta = blockIdx.x;
    const int dir = cta >> 5;
    const int bgp = (cta >> 3) & 3;
    const int cg  = cta & 7;
    const int bgA = bgp;
    const int bgB = bgp + 4;
    const float* Wh = dir ? Wh_b : Wh_f;
    const int tid = threadIdx.x;

    // load Wh slice (shared by both groups): sm_wh[k*128 + g*32 + m]
    {
        const float4* W4 = (const float4*)Wh;
        float4* d4 = (float4*)sm_wh;
        for (int u = tid; u < 8192; u += 128) {
            int k = u >> 5, l4 = u & 31;
            d4[u] = W4[(k * 1024 + (l4 >> 3) * 256 + cg * 32 + (l4 & 7) * 4) >> 2];
        }
    }
    for (int u = tid; u < 1024; u += 128) { sm_hdA[u] = 0ull; sm_hdB[u] = 0ull; }

    // group max seq lens
    const int4 slsA = *(const int4*)&seq_len[bgA * 4];
    const int4 slsB = *(const int4*)&seq_len[bgB * 4];
    const int mxA = max(max(slsA.x, slsA.y), max(slsA.z, slsA.w));
    const int mxB = max(max(slsB.x, slsB.y), max(slsB.z, slsB.w));

    // GEMM mapping
    const int j8 = tid & 15;          // col oct: local cols 8*j8 .. 8*j8+7
    const int bh = (tid >> 4) & 1;    // local batches 2bh, 2bh+1
    const int kh = tid >> 5;          // k quarter (== warp id)
    const int kbase = kh * 64;
    const int lane = tid & 31;
    // combine mapping
    const int m  = tid & 31;
    const int bl = tid >> 5;
    const int slA = seq_len[bgA * 4 + bl];
    const int slB = seq_len[bgB * 4 + bl];
    const int ncol = cg * 32 + m;

    const int gq  = j8 >> 2;
    const int c0g = gq * 256 + cg * 32 + ((8 * j8) & 31);
    const int b0A = bgA * 4 + 2 * bh;
    const int b0B = bgB * 4 + 2 * bh;

    int* ctrA = &g_ctr[(dir * 8 + bgA) * 32];
    int* ctrB = &g_ctr[(dir * 8 + bgB) * 32];
    ull* slabA = &g_hx[(size_t)(dir * 8 + bgA) * 2048];
    ull* slabB = &g_hx[(size_t)(dir * 8 + bgB) * 2048];

    float cA = 0.f, hA = 0.f, cB = 0.f, hB = 0.f;

    // backward: g_hist is exactly zero for t >= mx (mask never fires, h stays 0)
    if (dir == 1) {
        const int col = tid & 31;
        const int tq  = tid >> 5;
        float4 z = make_float4(0.f, 0.f, 0.f, 0.f);
        for (int tt = mxA + tq; tt < TT; tt += 4)
            *(float4*)&g_hist[((size_t)(TT + tt) * HH + cg * 32 + col) * BB + bgA * 4] = z;
        for (int tt = mxB + tq; tt < TT; tt += 4)
            *(float4*)&g_hist[((size_t)(TT + tt) * HH + cg * 32 + col) * BB + bgB * 4] = z;
    }

    // prefetch gx for first computed step of each group (kh==0 threads carry)
    ulonglong2 qA00, qA01, qA10, qA11, qB00, qB01, qB10, qB11;
    if (kh == 0) {
        int t0A = dir ? (mxA - 1) : 0;
        int t0B = dir ? (mxB - 1) : 0;
        size_t baseA = ((size_t)(dir * TT + t0A) * 32 + b0A) * 1024 + c0g;
        size_t baseB = ((size_t)(dir * TT + t0B) * 32 + b0B) * 1024 + c0g;
        qA00 = *(const ulonglong2*)(g_gx + baseA);
        qA01 = *(const ulonglong2*)(g_gx + baseA + 4);
        qA10 = *(const ulonglong2*)(g_gx + baseA + 1024);
        qA11 = *(const ulonglong2*)(g_gx + baseA + 1028);
        qB00 = *(const ulonglong2*)(g_gx + baseB);
        qB01 = *(const ulonglong2*)(g_gx + baseB + 4);
        qB10 = *(const ulonglong2*)(g_gx + baseB + 1024);
        qB11 = *(const ulonglong2*)(g_gx + baseB + 1028);
    }
    __syncthreads();

    // one LSTM step for one group (all threads call; contains block barriers)
    auto phase = [&](int p, int mxg, int slg, int bgg, int b0g,
                     int* ctrp, ull* slab, ull* sm_hdg, float* sm_hog,
                     float& c_reg, float& h_prev,
                     ulonglong2& q00, ulonglong2& q01,
                     ulonglong2& q10, ulonglong2& q11) {
        const int t = dir ? (mxg - 1 - p) : p;
        const int par = p & 1;

        // acquire previous h: poll (latency hidden by other group's phase),
        // then each warp stages only its own k-slice.
        if (p > 0) {
            while (ld_acquire(ctrp) < 8 * p) { }
            const ulonglong2* src = (const ulonglong2*)(slab + ((p - 1) & 1) * 1024);
            ulonglong2* dst = (ulonglong2*)sm_hdg;
            #pragma unroll
            for (int i = 0; i < 4; i++) {
                int idx = kh * 128 + i * 32 + lane;
                dst[idx] = src[idx];
            }
            __syncwarp();
        }

        // ---- GEMM: 8 cols x 2 batches x 64 k per thread ----
        ull a0, a1, a2, a3, a4, a5, a6, a7;
        if (kh == 0) {
            a0 = q00.x; a2 = q00.y; a4 = q01.x; a6 = q01.y;   // batch b0
            a1 = q10.x; a3 = q10.y; a5 = q11.x; a7 = q11.y;   // batch b0+1
        } else {
            a0 = a1 = a2 = a3 = a4 = a5 = a6 = a7 = 0ull;
        }
        #pragma unroll 8
        for (int kk = 0; kk < 64; kk++) {
            int k = kbase + kk;
            ulonglong2 w01 = *(const ulonglong2*)&sm_wh[k * 128 + 8 * j8];
            ulonglong2 w23 = *(const ulonglong2*)&sm_wh[k * 128 + 8 * j8 + 4];
            ulonglong2 hq  = *(const ulonglong2*)&sm_hdg[k * 4 + 2 * bh];
            a0 = ffma2(w01.x, hq.x, a0);  a1 = ffma2(w01.x, hq.y, a1);
            a2 = ffma2(w01.y, hq.x, a2);  a3 = ffma2(w01.y, hq.y, a3);
            a4 = ffma2(w23.x, hq.x, a4);  a5 = ffma2(w23.x, hq.y, a5);
            a6 = ffma2(w23.y, hq.x, a6);  a7 = ffma2(w23.y, hq.y, a7);
        }

        // prefetch next step's gx (lands during other group's phase)
        if (kh == 0 && p < mxg - 1) {
            int tn = dir ? (t - 1) : (t + 1);
            size_t base = ((size_t)(dir * TT + tn) * 32 + b0g) * 1024 + c0g;
            q00 = *(const ulonglong2*)(g_gx + base);
            q01 = *(const ulonglong2*)(g_gx + base + 4);
            q10 = *(const ulonglong2*)(g_gx + base + 1024);
            q11 = *(const ulonglong2*)(g_gx + base + 1028);
        }

        // ---- flat reduction: kh=1,2,3 write partials, kh=0 accumulates ----
        const int slot = (bh * 16 + j8) * 4;
        if (kh != 0) {
            ulonglong2* d = &sm_part[(kh - 1) * 128 + slot];
            d[0] = make_ulonglong2(a0, a1); d[1] = make_ulonglong2(a2, a3);
            d[2] = make_ulonglong2(a4, a5); d[3] = make_ulonglong2(a6, a7);
        }
        __syncthreads();   // A: partials visible
        if (kh == 0) {
            const ulonglong2* s0 = &sm_part[0 * 128 + slot];
            const ulonglong2* s1 = &sm_part[1 * 128 + slot];
            const ulonglong2* s2 = &sm_part[2 * 128 + slot];
            ulonglong2 p00 = s0[0], p01 = s0[1], p02 = s0[2], p03 = s0[3];
            ulonglong2 p10 = s1[0], p11 = s1[1], p12 = s1[2], p13 = s1[3];
            ulonglong2 p20 = s2[0], p21 = s2[1], p22 = s2[2], p23 = s2[3];
            a0 = padd2(padd2(a0, p00.x), padd2(p10.x, p20.x));
            a1 = padd2(padd2(a1, p00.y), padd2(p10.y, p20.y));
            a2 = padd2(padd2(a2, p01.x), padd2(p11.x, p21.x));
            a3 = padd2(padd2(a3, p01.y), padd2(p11.y, p21.y));
            a4 = padd2(padd2(a4, p02.x), padd2(p12.x, p22.x));
            a5 = padd2(padd2(a5, p02.y), padd2(p12.y, p22.y));
            a6 = padd2(padd2(a6, p03.x), padd2(p13.x, p23.x));
            a7 = padd2(padd2(a7, p03.y), padd2(p13.y, p23.y));
            float2 f0 = unp(a0), f2 = unp(a2), f4 = unp(a4), f6 = unp(a6);
            float2 f1 = unp(a1), f3 = unp(a3), f5 = unp(a5), f7 = unp(a7);
            int lbase = 8 * j8;
            float* gbuf = sm_g + par * 512;
            *(float4*)&gbuf[(2 * bh)     * 128 + lbase]     = make_float4(f0.x, f0.y, f2.x, f2.y);
            *(float4*)&gbuf[(2 * bh)     * 128 + lbase + 4] = make_float4(f4.x, f4.y, f6.x, f6.y);
            *(float4*)&gbuf[(2 * bh + 1) * 128 + lbase]     = make_float4(f1.x, f1.y, f3.x, f3.y);
            *(float4*)&gbuf[(2 * bh + 1) * 128 + lbase + 4] = make_float4(f5.x, f5.y, f7.x, f7.y);
        }
        __syncthreads();   // B: gates visible

        // ---- combine: thread = (h col m, batch bl) ----
        const float* gbuf = sm_g + par * 512;
        float gi_ = gbuf[bl * 128 +  0 + m];
        float gf_ = gbuf[bl * 128 + 32 + m];
        float gc_ = gbuf[bl * 128 + 64 + m];
        float go_ = gbuf[bl * 128 + 96 + m];
        float c_new = sigf(gf_) * c_reg + sigf(gi_) * tanhf_(gc_);
        float h_new = sigf(go_) * tanhf_(c_new);
        bool  msk = (t < slg);
        if (msk) c_reg = c_new;
        float h_out = msk ? h_new : h_prev;
        h_prev = h_out;

        // publish for peers + stage for coalesced hist store
        if (p < mxg - 1)
            slab[(p & 1) * 1024 + ncol * 4 + bl] = dup2(h_out);
        sm_hog[par * 128 + m * 4 + bl] = h_out;
        __syncthreads();   // C: slab stores ordered before release; sm_ho visible

        if (tid == 0 && p < mxg - 1) red_release_add(ctrp, 1);
        if (tid < 32) {
            float4 v = *(const float4*)&sm_hog[par * 128 + tid * 4];
            *(float4*)&g_hist[((size_t)(dir * TT + t) * HH + cg * 32 + tid) * BB + bgg * 4] = v;
        }
        // sm_g/sm_part shared A/B: phase barriers order all cross-phase reuse.
    };

    const int nmax = max(mxA, mxB);
    for (int p = 0; p < nmax; p++) {
        if (p < mxA)
            phase(p, mxA, slA, bgA, b0A, ctrA, slabA, sm_hdA, sm_hoA,
                  cA, hA, qA00, qA01, qA10, qA11);
        if (p < mxB)
            phase(p, mxB, slB, bgB, b0B, ctrB, slabB, sm_hdB, sm_hoB,
                  cB, hB, qB00, qB01, qB10, qB11);
    }

    // forward: g_hist for t >= mx is the frozen h (per-batch, maintained by mask)
    if (dir == 0) {
        const int col = tid & 31;
        const int tq  = tid >> 5;
        {
            const int lastpar = (mxA - 1) & 1;
            float4 v = *(const float4*)&sm_hoA[lastpar * 128 + col * 4];
            for (int tt = mxA + tq; tt < TT; tt += 4)
                *(float4*)&g_hist[((size_t)tt * HH + cg * 32 + col) * BB + bgA * 4] = v;
        }
        {
            const int lastpar = (mxB - 1) & 1;
            float4 v = *(const float4*)&sm_hoB[lastpar * 128 + col * 4];
            for (int tt = mxB + tq; tt < TT; tt += 4)
                *(float4*)&g_hist[((size_t)tt * HH + cg * 32 + col) * BB + bgB * 4] = v;
        }
    }
}

// ---------------- kernel C: output projection + log_softmax ----------------
__global__ void proj_kernel(const float* __restrict__ out_W,
                            const float* __restrict__ out_b) {
    extern __shared__ float sm[];
    float* hsm = sm;                       // 512*32
    float* wsm = sm + 512 * 32;            // 512*32
    float* lsm = wsm + 512 * 32;           // 32*33
    float* lse = lsm + 32 * 33;            // 32

    const int t   = blockIdx.x;
    const int tid = threadIdx.x;

    float4* hd = (float4*)hsm;
    const float4* h0 = (const float4*)(g_hist + (size_t)t * HH * BB);
    const float4* h1 = (const float4*)(g_hist + (size_t)(TT + t) * HH * BB);
    #pragma unroll
    for (int i = 0; i < 16; i++) {
        int idx = tid + i * 256;
        hd[idx] = (idx < 2048) ? h0[idx] : h1[idx - 2048];
    }
    float4* wd = (float4*)wsm;
    const float4* w4 = (const float4*)out_W;
    #pragma unroll
    for (int i = 0; i < 16; i++) {
        int idx = tid + i * 256;
        wd[idx] = w4[idx];
    }
    __syncthreads();

    const int b  = tid & 31;
    const int cg = tid >> 5;
    float acc[4];
    #pragma unroll
    for (int jj = 0; jj < 4; jj++) acc[jj] = out_b[cg * 4 + jj];
    #pragma unroll 8
    for (int k = 0; k < 512; k++) {
        float  hv = hsm[k * 32 + b];
        float4 ww = *(const float4*)&wsm[k * 32 + cg * 4];
        acc[0] += hv * ww.x; acc[1] += hv * ww.y; acc[2] += hv * ww.z; acc[3] += hv * ww.w;
    }
    #pragma unroll
    for (int jj = 0; jj < 4; jj++) lsm[b * 33 + cg * 4 + jj] = acc[jj];
    __syncthreads();

    if (tid < 32) {
        float mx = -1e30f;
        #pragma unroll
        for (int c = 0; c < 32; c++) mx = fmaxf(mx, lsm[tid * 33 + c]);
        float ssum = 0.f;
        #pragma unroll
        for (int c = 0; c < 32; c++) ssum += expf(lsm[tid * 33 + c] - mx);
        lse[tid] = mx + logf(ssum);
    }
    __syncthreads();

    float l = lse[b];
    #pragma unroll
    for (int jj = 0; jj < 4; jj++)
        g_logits[(size_t)t * BB * CC + b * CC + cg * 4 + jj] = acc[jj] - l;
}

// ---------------- kernel D: CRF normalizer + gold score (4 warps/batch) ----------------
__global__ void __launch_bounds__(128) crf_kernel(
        const int* __restrict__ seq_len,
        const int* __restrict__ target,
        const float* __restrict__ trans,
        const float* __restrict__ start_trans,
        const float* __restrict__ end_trans,
        float* __restrict__ out) {
    __shared__ float sm_m[2][4][32];
    __shared__ float sm_s[2][4][32];
    __shared__ float sm_r[4];

    const int b   = blockIdx.x;
    const int tid = threadIdx.x;
    const int j   = tid & 31;
    const int w   = tid >> 5;
    const int sl  = seq_len[b];

    float tr8[8];
    #pragma unroll
    for (int ii = 0; ii < 8; ii++) tr8[ii] = trans[(8 * w + ii) * 32 + j];

    float alpha = g_logits[(size_t)b * CC + j] + start_trans[j];

    for (int t = 1; t < sl; t++) {
        float emit = g_logits[(size_t)t * BB * CC + b * CC + j];
        float v[8];
        #pragma unroll
        for (int ii = 0; ii < 8; ii++)
            v[ii] = __shfl_sync(0xffffffffu, alpha, 8 * w + ii) + tr8[ii];
        float mw = fmaxf(fmaxf(fmaxf(v[0], v[1]), fmaxf(v[2], v[3])),
                         fmaxf(fmaxf(v[4], v[5]), fmaxf(v[6], v[7])));
        float sw = 0.f;
        #pragma unroll
        for (int ii = 0; ii < 8; ii++) sw += __expf(v[ii] - mw);

        int par = t & 1;
        sm_m[par][w][j] = mw;
        sm_s[par][w][j] = sw;
        __syncthreads();

        float m0 = sm_m[par][0][j], m1 = sm_m[par][1][j];
        float m2 = sm_m[par][2][j], m3 = sm_m[par][3][j];
        float M = fmaxf(fmaxf(m0, m1), fmaxf(m2, m3));
        float S = sm_s[par][0][j] * __expf(m0 - M) + sm_s[par][1][j] * __expf(m1 - M)
                + sm_s[par][2][j] * __expf(m2 - M) + sm_s[par][3][j] * __expf(m3 - M);
        alpha = M + __logf(S) + emit;
    }

    float vv = alpha + end_trans[j];
    float mx = vv;
    #pragma unroll
    for (int o = 16; o > 0; o >>= 1) mx = fmaxf(mx, __shfl_xor_sync(0xffffffffu, mx, o));
    float se = __expf(vv - mx);
    #pragma unroll
    for (int o = 16; o > 0; o >>= 1) se += __shfl_xor_sync(0xffffffffu, se, o);
    float norm = mx + logf(se);

    float gs = 0.f;
    for (int t = tid; t < sl; t += 128) {
        int tg = target[b * TT + t];
        gs += g_logits[(size_t)t * BB * CC + b * CC + tg];
        if (t >= 1) gs += trans[target[b * TT + t - 1] * 32 + tg];
    }
    #pragma unroll
    for (int o = 16; o > 0; o >>= 1) gs += __shfl_xor_sync(0xffffffffu, gs, o);
    if (j == 0) sm_r[w] = gs;
    __syncthreads();

    if (tid == 0) {
        float g = sm_r[0] + sm_r[1] + sm_r[2] + sm_r[3]
                + start_trans[target[b * TT]] + end_trans[target[b * TT + sl - 1]];
        out[b] = norm - g;
    }
}

// ---------------- launch ----------------
extern "C" void kernel_launch(void* const* d_in, const int* in_sizes, int n_in,
                              void* d_out, int out_size) {
    const int*   chars        = (const int*)d_in[0];
    const int*   bigrams      = (const int*)d_in[1];
    const int*   seq_len      = (const int*)d_in[2];
    const int*   target       = (const int*)d_in[3];
    const float* char_table   = (const float*)d_in[4];
    const float* bigram_table = (const float*)d_in[5];
    const float* Wi_f         = (const float*)d_in[6];
    const float* Wh_f         = (const float*)d_in[7];
    const float* b_f          = (const float*)d_in[8];
    const float* Wi_b         = (const float*)d_in[9];
    const float* Wh_b         = (const float*)d_in[10];
    const float* b_b          = (const float*)d_in[11];
    const float* out_W        = (const float*)d_in[12];
    const float* out_b        = (const float*)d_in[13];
    const float* trans        = (const float*)d_in[14];
    const float* start_trans  = (const float*)d_in[15];
    const float* end_trans    = (const float*)d_in[16];
    float* out = (float*)d_out;

    const int SMEM_A = 32768 + 65536;                                       // 98304
    const int SMEM_S = 131072 + 8192 + 8192 + 4096 + 6144 + 1024 + 1024;    // 159744
    const int SMEM_P = (512 * 32 * 2 + 32 * 33 + 32) * (int)sizeof(float);  // 135424

    cudaFuncSetAttribute(wi_gemm_kernel, cudaFuncAttributeMaxDynamicSharedMemorySize, SMEM_A);
    cudaFuncSetAttribute(scan_kernel,    cudaFuncAttributeMaxDynamicSharedMemorySize, SMEM_S);
    cudaFuncSetAttribute(proj_kernel,    cudaFuncAttributeMaxDynamicSharedMemorySize, SMEM_P);

    init_kernel<<<2, 256>>>();

    dim3 ga(TT, 16);
    wi_gemm_kernel<<<ga, 256, SMEM_A>>>(chars, bigrams, char_table, bigram_table,
                                        Wi_f, b_f, Wi_b, b_b);

    scan_kernel<<<64, 128, SMEM_S>>>(Wh_f, Wh_b, seq_len);

    proj_kernel<<<TT, 256, SMEM_P>>>(out_W, out_b);

    crf_kernel<<<BB, 128>>>(seq_len, target, trans, start_trans, end_trans, out);
}

// round 16
// speedup vs baseline: 1.4660x; 1.4660x over previous
#include <cuda_runtime.h>
#include <math.h>
#include <stdint.h>

#define BB   32
#define TT   512
#define HH   256
#define CC   32
#define G4   1024   // 4*H
#define DD   256

typedef unsigned long long ull;

// ---------------- scratch (no allocations allowed) ----------------
// gx layout: [dir][t][b][col]  (col fastest, 1024 per dir)
__device__ float g_gx[(size_t)2 * TT * BB * G4];     // 134 MB
__device__ float g_hist[(size_t)2 * TT * HH * BB];   // [dir][t][n][b]  33 MB
__device__ float g_logits[(size_t)TT * BB * CC];     // [t][b][c]        2 MB
// h exchange slabs per group: [16][parity][256 cols][4 b] duplicated ull
__device__ ull   g_hx[16 * 2048];                    // 256 KB
__device__ int   g_ctr[16 * 32];                     // 1 counter per group, 128B apart

// ---------------- packed fp32x2 helpers ----------------
__device__ __forceinline__ ull ffma2(ull a, ull b, ull c) {
    ull d;
    asm("fma.rn.f32x2 %0, %1, %2, %3;" : "=l"(d) : "l"(a), "l"(b), "l"(c));
    return d;
}
__device__ __forceinline__ ull padd2(ull a, ull b) {
    ull d;
    asm("add.rn.f32x2 %0, %1, %2;" : "=l"(d) : "l"(a), "l"(b));
    return d;
}
__device__ __forceinline__ ull dup2(float x) {
    ull p = (ull)__float_as_uint(x);
    return p | (p << 32);
}
__device__ __forceinline__ float2 unp(ull v) {
    float2 f;
    asm("mov.b64 {%0, %1}, %2;" : "=f"(f.x), "=f"(f.y) : "l"(v));
    return f;
}

__device__ __forceinline__ float sigf(float x)  { return __fdividef(1.f, 1.f + __expf(-x)); }
__device__ __forceinline__ float tanhf_(float x){ return __fdividef(2.f, 1.f + __expf(-2.f * x)) - 1.f; }

// release-add / acquire-load pair
__device__ __forceinline__ void red_release_add(int* p, int v) {
    asm volatile("red.release.gpu.global.add.s32 [%0], %1;" :: "l"(p), "r"(v) : "memory");
}
__device__ __forceinline__ int ld_acquire(const int* p) {
    int v;
    asm volatile("ld.acquire.gpu.global.b32 %0, [%1];" : "=r"(v) : "l"(p) : "memory");
    return v;
}
// L1-bypassing 8B load (slab reads must not hit stale L1 lines)
__device__ __forceinline__ ull ldcg64(const ull* p) {
    ull v;
    asm volatile("ld.global.cg.u64 %0, [%1];" : "=l"(v) : "l"(p));
    return v;
}

// ---------------- init: zero counters each replay ----------------
__global__ void init_kernel() {
    int i = blockIdx.x * blockDim.x + threadIdx.x;
    if (i < 16 * 32) g_ctr[i] = 0;
}

// ---------------- kernel A: embedding gather + x@Wi + bias (fp32x2) ----------------
// grid (512, 16): x = t, y = dir*8 + colblock(128 cols). 256 threads.
__global__ void __launch_bounds__(256) wi_gemm_kernel(
        const int* __restrict__ chars,
        const int* __restrict__ bigrams,
        const float* __restrict__ char_table,
        const float* __restrict__ bigram_table,
        const float* __restrict__ Wi_f,
        const float* __restrict__ bias_f,
        const float* __restrict__ Wi_b,
        const float* __restrict__ bias_b) {
    extern __shared__ float sm[];
    float* a_sm = sm;                       // 8192 floats = 32KB
    ull*   wd_sm = (ull*)(sm + 8192);       // 8192 ull = 64KB

    const int t   = blockIdx.x;
    const int yid = blockIdx.y;
    const int dir = yid >> 3;
    const int cb  = yid & 7;
    const float* Wi   = dir ? Wi_b  : Wi_f;
    const float* bias = dir ? bias_b : bias_f;

    const int tid = threadIdx.x;

    // gather emb -> a_sm[k][b]
    {
        const int b    = tid & 31;
        const int part = tid >> 5;
        const int ci = chars[b * TT + t];
        const int bi = bigrams[b * TT + t];
        #pragma unroll
        for (int i = 0; i < 8; i++) {
            int k4 = part * 8 + i;
            float4 v;
            if (k4 < 32) v = ((const float4*)char_table)[(size_t)ci * 32 + k4];
            else         v = ((const float4*)bigram_table)[(size_t)bi * 32 + (k4 - 32)];
            a_sm[(k4 * 4 + 0) * 32 + b] = v.x;
            a_sm[(k4 * 4 + 1) * 32 + b] = v.y;
            a_sm[(k4 * 4 + 2) * 32 + b] = v.z;
            a_sm[(k4 * 4 + 3) * 32 + b] = v.w;
        }
    }

    const int cg = tid >> 3;   // cols cg*4 .. cg*4+3
    const int bq = tid & 7;    // batches 4bq .. 4bq+3
    ull acc[8];
    #pragma unroll
    for (int i = 0; i < 8; i++) acc[i] = 0ull;

    const ulonglong2* a2 = (const ulonglong2*)a_sm;

    for (int ch = 0; ch < 4; ch++) {
        const int k0 = ch * 64;
        __syncthreads();
        for (int u = tid; u < 8192; u += 256) {
            int kk  = u >> 7;
            int col = u & 127;
            float wv = Wi[(size_t)(k0 + kk) * G4 + cb * 128 + col];
            wd_sm[u] = dup2(wv);
        }
        __syncthreads();
        #pragma unroll 8
        for (int kk = 0; kk < 64; kk++) {
            ulonglong2 hv = a2[(k0 + kk) * 8 + bq];
            const ull* wr = &wd_sm[kk * 128 + cg * 4];
            #pragma unroll
            for (int c = 0; c < 4; c++) {
                ull wd = wr[c];
                acc[2 * c]     = ffma2(hv.x, wd, acc[2 * c]);
                acc[2 * c + 1] = ffma2(hv.y, wd, acc[2 * c + 1]);
            }
        }
    }

    // transpose in smem, then store as [dir][t][b][col]
    __syncthreads();
    {
        #pragma unroll
        for (int cc = 0; cc < 4; cc++) {
            int col = cg * 4 + cc;
            ull b2 = dup2(bias[cb * 128 + col]);
            float2 v01 = unp(padd2(acc[2 * cc],     b2));
            float2 v23 = unp(padd2(acc[2 * cc + 1], b2));
            a_sm[(bq * 4 + 0) * 129 + col] = v01.x;
            a_sm[(bq * 4 + 1) * 129 + col] = v01.y;
            a_sm[(bq * 4 + 2) * 129 + col] = v23.x;
            a_sm[(bq * 4 + 3) * 129 + col] = v23.y;
        }
    }
    __syncthreads();
    {
        float* outp = g_gx + (size_t)(dir * TT + t) * (32 * 1024) + cb * 128;
        #pragma unroll
        for (int i = 0; i < 4; i++) {
            int idx = tid + i * 256;
            int b = idx >> 5, c4 = idx & 31;
            float4 v;
            v.x = a_sm[b * 129 + c4 * 4 + 0];
            v.y = a_sm[b * 129 + c4 * 4 + 1];
            v.z = a_sm[b * 129 + c4 * 4 + 2];
            v.w = a_sm[b * 129 + c4 * 4 + 3];
            *(float4*)(outp + (size_t)b * 1024 + c4 * 4) = v;
        }
    }
}

// ---------------- kernel B: recurrent scan, 8-CTA groups, single-barrier step ----------------
// grid 128 CTAs of 128 threads: CTA = (dir, bg in 0..7, cg in 0..7).
// Gate remap: thread (j8,bh) accumulates cols {g*256 + cg*32 + 2j8 + c} for g=0..3, c=0..1,
// packed over 2 batches. After reduction, warp 0 holds i,f,g,o per (col,batch) in registers:
// combine + slab publish + hist store are warp-0-local -> barriers B and C eliminated.
__global__ void __launch_bounds__(128, 1)
scan_kernel(const float* __restrict__ Wh_f,
            const float* __restrict__ Wh_b,
            const int* __restrict__ seq_len) {
    extern __shared__ float sm[];
    float*      sm_wh   = sm;                          // [256][128] f32 = 128KB (permuted)
    ull*        sm_hd   = (ull*)(sm + 32768);          // [256][4] dup ull = 8KB
    ulonglong2* sm_part = (ulonglong2*)(sm_hd + 1024); // [2 par][3][128] u2 = 12KB
    float*      sm_ho   = (float*)(sm_part + 768);     // [2 par][128] = 1KB

    const int cta = blockIdx.x;
    const int dir = cta >> 6;
    const int bg  = (cta >> 3) & 7;
    const int cg  = cta & 7;
    const float* Wh = dir ? Wh_b : Wh_f;
    const int tid  = threadIdx.x;
    const int lane = tid & 31;

    // permuted Wh load: sm_wh[k*128 + j8*8 + g*2 + c] = Wh[k][g*256 + cg*32 + 2*j8 + c]
    // iterate float2 pairs ordered (k, g, j8) -> consecutive threads = consecutive src cols
    {
        const float2* W2 = (const float2*)Wh;
        for (int v = tid; v < 16384; v += 128) {
            int j8v = v & 15;
            int gv  = (v >> 4) & 3;
            int kv  = v >> 6;
            float2 w = W2[(kv * 1024 + gv * 256 + cg * 32 + j8v * 2) >> 1];
            *(float2*)&sm_wh[kv * 128 + j8v * 8 + gv * 2] = w;
        }
    }
    for (int u = tid; u < 1024; u += 128) sm_hd[u] = 0ull;

    // group max seq len
    const int4 sls = *(const int4*)&seq_len[bg * 4];
    const int mx = max(max(sls.x, sls.y), max(sls.z, sls.w));

    // GEMM mapping
    const int j8 = tid & 15;          // 2 h-cols: n0 = cg*32 + 2*j8, n0+1
    const int bh = (tid >> 4) & 1;    // local batches 2bh, 2bh+1
    const int kh = tid >> 5;          // k quarter (== warp id)
    const int kbase = kh * 64;

    const int n0  = cg * 32 + 2 * j8;
    const int sl0 = seq_len[bg * 4 + 2 * bh];
    const int sl1 = seq_len[bg * 4 + 2 * bh + 1];

    int* ctrp = &g_ctr[(dir * 8 + bg) * 32];
    ull* slab = &g_hx[(size_t)(dir * 8 + bg) * 2048];

    // warp-0 combine state: [c][b]
    float cs00 = 0.f, cs01 = 0.f, cs10 = 0.f, cs11 = 0.f;
    float hp00 = 0.f, hp01 = 0.f, hp10 = 0.f, hp11 = 0.f;

    // backward: g_hist is exactly zero for t >= mx (mask never fires, h stays 0)
    if (dir == 1) {
        const int col = tid & 31;
        const int tq  = tid >> 5;
        float4 z = make_float4(0.f, 0.f, 0.f, 0.f);
        for (int tt = mx + tq; tt < TT; tt += 4)
            *(float4*)&g_hist[((size_t)(TT + tt) * HH + cg * 32 + col) * BB + bg * 4] = z;
    }

    // gx prefetch (warp 0 carries): q[2g+b] = gates for (gate g, cols n0..n0+1, batch 2bh+b)
    ull q0, q1, q2, q3, q4, q5, q6, q7;
    if (kh == 0) {
        int t0 = dir ? (mx - 1) : 0;
        size_t base = ((size_t)(dir * TT + t0) * 32 + bg * 4 + 2 * bh) * 1024 + n0;
        q0 = *(const ull*)(g_gx + base);          q1 = *(const ull*)(g_gx + base + 1024);
        q2 = *(const ull*)(g_gx + base + 256);    q3 = *(const ull*)(g_gx + base + 1280);
        q4 = *(const ull*)(g_gx + base + 512);    q5 = *(const ull*)(g_gx + base + 1536);
        q6 = *(const ull*)(g_gx + base + 768);    q7 = *(const ull*)(g_gx + base + 1792);
    }
    __syncthreads();

    for (int p = 0; p < mx; p++) {
        const int t = dir ? (mx - 1 - p) : p;
        const int par = p & 1;

        // acquire previous h; each warp stages only its own k-slice (L1-bypassing loads)
        if (p > 0) {
            const int tgt = 8 * p;
            while (ld_acquire(ctrp) < tgt) { }
            const ull* src = slab + ((p - 1) & 1) * 1024;
            #pragma unroll
            for (int i = 0; i < 4; i++) {
                int idx = kh * 128 + i * 32 + lane;
                sm_hd[idx] = ldcg64(src + idx);
            }
            __syncwarp();
        }

        // ---- GEMM: 8 (gate,col) accum x 2 batches x 64 k per thread ----
        ull a0, a1, a2, a3, a4, a5, a6, a7;
        if (kh == 0) { a0 = q0; a1 = q1; a2 = q2; a3 = q3; a4 = q4; a5 = q5; a6 = q6; a7 = q7; }
        else         { a0 = a1 = a2 = a3 = a4 = a5 = a6 = a7 = 0ull; }
        #pragma unroll 8
        for (int kk = 0; kk < 64; kk++) {
            int k = kbase + kk;
            ulonglong2 w01 = *(const ulonglong2*)&sm_wh[k * 128 + 8 * j8];      // gates i,f
            ulonglong2 w23 = *(const ulonglong2*)&sm_wh[k * 128 + 8 * j8 + 4];  // gates g,o
            ulonglong2 hq  = *(const ulonglong2*)&sm_hd[k * 4 + 2 * bh];
            a0 = ffma2(w01.x, hq.x, a0);  a1 = ffma2(w01.x, hq.y, a1);
            a2 = ffma2(w01.y, hq.x, a2);  a3 = ffma2(w01.y, hq.y, a3);
            a4 = ffma2(w23.x, hq.x, a4);  a5 = ffma2(w23.x, hq.y, a5);
            a6 = ffma2(w23.y, hq.x, a6);  a7 = ffma2(w23.y, hq.y, a7);
        }

        // prefetch next step's gx (hidden behind combine/poll of this step)
        if (kh == 0 && p < mx - 1) {
            int tn = dir ? (t - 1) : (t + 1);
            size_t base = ((size_t)(dir * TT + tn) * 32 + bg * 4 + 2 * bh) * 1024 + n0;
            q0 = *(const ull*)(g_gx + base);          q1 = *(const ull*)(g_gx + base + 1024);
            q2 = *(const ull*)(g_gx + base + 256);    q3 = *(const ull*)(g_gx + base + 1280);
            q4 = *(const ull*)(g_gx + base + 512);    q5 = *(const ull*)(g_gx + base + 1536);
            q6 = *(const ull*)(g_gx + base + 768);    q7 = *(const ull*)(g_gx + base + 1792);
        }

        // ---- partials: warps 1..3 write (parity double-buffered) ----
        const int slot = (bh * 16 + j8) * 4;
        if (kh != 0) {
            ulonglong2* d = &sm_part[par * 384 + (kh - 1) * 128 + slot];
            d[0] = make_ulonglong2(a0, a1); d[1] = make_ulonglong2(a2, a3);
            d[2] = make_ulonglong2(a4, a5); d[3] = make_ulonglong2(a6, a7);
        }
        __syncthreads();   // A: the only block barrier per step

        if (kh == 0) {
            const ulonglong2* s0 = &sm_part[par * 384 + 0 * 128 + slot];
            const ulonglong2* s1 = &sm_part[par * 384 + 1 * 128 + slot];
            const ulonglong2* s2 = &sm_part[par * 384 + 2 * 128 + slot];
            ulonglong2 p00 = s0[0], p01 = s0[1], p02 = s0[2], p03 = s0[3];
            ulonglong2 p10 = s1[0], p11 = s1[1], p12 = s1[2], p13 = s1[3];
            ulonglong2 p20 = s2[0], p21 = s2[1], p22 = s2[2], p23 = s2[3];
            a0 = padd2(padd2(a0, p00.x), padd2(p10.x, p20.x));
            a1 = padd2(padd2(a1, p00.y), padd2(p10.y, p20.y));
            a2 = padd2(padd2(a2, p01.x), padd2(p11.x, p21.x));
            a3 = padd2(padd2(a3, p01.y), padd2(p11.y, p21.y));
            a4 = padd2(padd2(a4, p02.x), padd2(p12.x, p22.x));
            a5 = padd2(padd2(a5, p02.y), padd2(p12.y, p22.y));
            a6 = padd2(padd2(a6, p03.x), padd2(p13.x, p23.x));
            a7 = padd2(padd2(a7, p03.y), padd2(p13.y, p23.y));

            // combine locally: gates (i,f,g,o) = (a0/a1, a2/a3, a4/a5, a6/a7), .x=c0 .y=c1
            float2 gi0 = unp(a0), gi1 = unp(a1);   // i: b0, b1
            float2 gf0 = unp(a2), gf1 = unp(a3);
            float2 gg0 = unp(a4), gg1 = unp(a5);
            float2 go0 = unp(a6), go1 = unp(a7);

            bool m0 = (t < sl0), m1 = (t < sl1);
            // state (c0,b0)
            {
                float cn = sigf(gf0.x) * cs00 + sigf(gi0.x) * tanhf_(gg0.x);
                float hn = sigf(go0.x) * tanhf_(cn);
                if (m0) cs00 = cn;
                hp00 = m0 ? hn : hp00;
            }
            // (c0,b1)
            {
                float cn = sigf(gf1.x) * cs01 + sigf(gi1.x) * tanhf_(gg1.x);
                float hn = sigf(go1.x) * tanhf_(cn);
                if (m1) cs01 = cn;
                hp01 = m1 ? hn : hp01;
            }
            // (c1,b0)
            {
                float cn = sigf(gf0.y) * cs10 + sigf(gi0.y) * tanhf_(gg0.y);
                float hn = sigf(go0.y) * tanhf_(cn);
                if (m0) cs10 = cn;
                hp10 = m0 ? hn : hp10;
            }
            // (c1,b1)
            {
                float cn = sigf(gf1.y) * cs11 + sigf(gi1.y) * tanhf_(gg1.y);
                float hn = sigf(go1.y) * tanhf_(cn);
                if (m1) cs11 = cn;
                hp11 = m1 ? hn : hp11;
            }

            // publish for peers (duplicated, parity slab)
            if (p < mx - 1) {
                ulonglong2 v0; v0.x = dup2(hp00); v0.y = dup2(hp01);
                *(ulonglong2*)&slab[par * 1024 + n0 * 4 + 2 * bh] = v0;
                ulonglong2 v1; v1.x = dup2(hp10); v1.y = dup2(hp11);
                *(ulonglong2*)&slab[par * 1024 + (n0 + 1) * 4 + 2 * bh] = v1;
            }
            // hist store (8B per col)
            {
                float2 h0 = make_float2(hp00, hp01);
                float2 h1 = make_float2(hp10, hp11);
                *(float2*)&g_hist[((size_t)(dir * TT + t) * HH + n0)     * BB + bg * 4 + 2 * bh] = h0;
                *(float2*)&g_hist[((size_t)(dir * TT + t) * HH + n0 + 1) * BB + bg * 4 + 2 * bh] = h1;
                // stage for forward tail-fill
                *(float2*)&sm_ho[par * 128 + (2 * j8)     * 4 + 2 * bh] = h0;
                *(float2*)&sm_ho[par * 128 + (2 * j8 + 1) * 4 + 2 * bh] = h1;
            }
            __syncwarp();   // order warp-0 slab stores before tid0's release
            if (tid == 0 && p < mx - 1) red_release_add(ctrp, 1);
        }
        // warps 1..3 proceed directly to next step's poll; sm_part parity
        // double-buffer + barrier A ordering protect all smem reuse.
    }
    __syncthreads();   // sm_ho final writes visible for tail-fill

    // forward: g_hist for t >= mx is the frozen h (per-batch, maintained by mask)
    if (dir == 0) {
        const int lastpar = (mx - 1) & 1;
        const int col = tid & 31;
        const int tq  = tid >> 5;
        float4 v = *(const float4*)&sm_ho[lastpar * 128 + col * 4];
        for (int tt = mx + tq; tt < TT; tt += 4)
            *(float4*)&g_hist[((size_t)tt * HH + cg * 32 + col) * BB + bg * 4] = v;
    }
}

// ---------------- kernel C: output projection + log_softmax ----------------
__global__ void proj_kernel(const float* __restrict__ out_W,
                            const float* __restrict__ out_b) {
    extern __shared__ float sm[];
    float* hsm = sm;                       // 512*32
    float* wsm = sm + 512 * 32;            // 512*32
    float* lsm = wsm + 512 * 32;           // 32*33
    float* lse = lsm + 32 * 33;            // 32

    const int t   = blockIdx.x;
    const int tid = threadIdx.x;

    float4* hd = (float4*)hsm;
    const float4* h0 = (const float4*)(g_hist + (size_t)t * HH * BB);
    const float4* h1 = (const float4*)(g_hist + (size_t)(TT + t) * HH * BB);
    #pragma unroll
    for (int i = 0; i < 16; i++) {
        int idx = tid + i * 256;
        hd[idx] = (idx < 2048) ? h0[idx] : h1[idx - 2048];
    }
    float4* wd = (float4*)wsm;
    const float4* w4 = (const float4*)out_W;
    #pragma unroll
    for (int i = 0; i < 16; i++) {
        int idx = tid + i * 256;
        wd[idx] = w4[idx];
    }
    __syncthreads();

    const int b  = tid & 31;
    const int cg = tid >> 5;
    float acc[4];
    #pragma unroll
    for (int jj = 0; jj < 4; jj++) acc[jj] = out_b[cg * 4 + jj];
    #pragma unroll 8
    for (int k = 0; k < 512; k++) {
        float  hv = hsm[k * 32 + b];
        float4 ww = *(const float4*)&wsm[k * 32 + cg * 4];
        acc[0] += hv * ww.x; acc[1] += hv * ww.y; acc[2] += hv * ww.z; acc[3] += hv * ww.w;
    }
    #pragma unroll
    for (int jj = 0; jj < 4; jj++) lsm[b * 33 + cg * 4 + jj] = acc[jj];
    __syncthreads();

    if (tid < 32) {
        float mx = -1e30f;
        #pragma unroll
        for (int c = 0; c < 32; c++) mx = fmaxf(mx, lsm[tid * 33 + c]);
        float ssum = 0.f;
        #pragma unroll
        for (int c = 0; c < 32; c++) ssum += expf(lsm[tid * 33 + c] - mx);
        lse[tid] = mx + logf(ssum);
    }
    __syncthreads();

    float l = lse[b];
    #pragma unroll
    for (int jj = 0; jj < 4; jj++)
        g_logits[(size_t)t * BB * CC + b * CC + cg * 4 + jj] = acc[jj] - l;
}

// ---------------- kernel D: CRF normalizer + gold score (4 warps/batch) ----------------
__global__ void __launch_bounds__(128) crf_kernel(
        const int* __restrict__ seq_len,
        const int* __restrict__ target,
        const float* __restrict__ trans,
        const float* __restrict__ start_trans,
        const float* __restrict__ end_trans,
        float* __restrict__ out) {
    __shared__ float sm_m[2][4][32];
    __shared__ float sm_s[2][4][32];
    __shared__ float sm_r[4];

    const int b   = blockIdx.x;
    const int tid = threadIdx.x;
    const int j   = tid & 31;
    const int w   = tid >> 5;
    const int sl  = seq_len[b];

    float tr8[8];
    #pragma unroll
    for (int ii = 0; ii < 8; ii++) tr8[ii] = trans[(8 * w + ii) * 32 + j];

    float alpha = g_logits[(size_t)b * CC + j] + start_trans[j];

    for (int t = 1; t < sl; t++) {
        float emit = g_logits[(size_t)t * BB * CC + b * CC + j];
        float v[8];
        #pragma unroll
        for (int ii = 0; ii < 8; ii++)
            v[ii] = __shfl_sync(0xffffffffu, alpha, 8 * w + ii) + tr8[ii];
        float mw = fmaxf(fmaxf(fmaxf(v[0], v[1]), fmaxf(v[2], v[3])),
                         fmaxf(fmaxf(v[4], v[5]), fmaxf(v[6], v[7])));
        float sw = 0.f;
        #pragma unroll
        for (int ii = 0; ii < 8; ii++) sw += __expf(v[ii] - mw);

        int par = t & 1;
        sm_m[par][w][j] = mw;
        sm_s[par][w][j] = sw;
        __syncthreads();

        float m0 = sm_m[par][0][j], m1 = sm_m[par][1][j];
        float m2 = sm_m[par][2][j], m3 = sm_m[par][3][j];
        float M = fmaxf(fmaxf(m0, m1), fmaxf(m2, m3));
        float S = sm_s[par][0][j] * __expf(m0 - M) + sm_s[par][1][j] * __expf(m1 - M)
                + sm_s[par][2][j] * __expf(m2 - M) + sm_s[par][3][j] * __expf(m3 - M);
        alpha = M + __logf(S) + emit;
    }

    float vv = alpha + end_trans[j];
    float mx = vv;
    #pragma unroll
    for (int o = 16; o > 0; o >>= 1) mx = fmaxf(mx, __shfl_xor_sync(0xffffffffu, mx, o));
    float se = __expf(vv - mx);
    #pragma unroll
    for (int o = 16; o > 0; o >>= 1) se += __shfl_xor_sync(0xffffffffu, se, o);
    float norm = mx + logf(se);

    float gs = 0.f;
    for (int t = tid; t < sl; t += 128) {
        int tg = target[b * TT + t];
        gs += g_logits[(size_t)t * BB * CC + b * CC + tg];
        if (t >= 1) gs += trans[target[b * TT + t - 1] * 32 + tg];
    }
    #pragma unroll
    for (int o = 16; o > 0; o >>= 1) gs += __shfl_xor_sync(0xffffffffu, gs, o);
    if (j == 0) sm_r[w] = gs;
    __syncthreads();

    if (tid == 0) {
        float g = sm_r[0] + sm_r[1] + sm_r[2] + sm_r[3]
                + start_trans[target[b * TT]] + end_trans[target[b * TT + sl - 1]];
        out[b] = norm - g;
    }
}

// ---------------- launch ----------------
extern "C" void kernel_launch(void* const* d_in, const int* in_sizes, int n_in,
                              void* d_out, int out_size) {
    const int*   chars        = (const int*)d_in[0];
    const int*   bigrams      = (const int*)d_in[1];
    const int*   seq_len      = (const int*)d_in[2];
    const int*   target       = (const int*)d_in[3];
    const float* char_table   = (const float*)d_in[4];
    const float* bigram_table = (const float*)d_in[5];
    const float* Wi_f         = (const float*)d_in[6];
    const float* Wh_f         = (const float*)d_in[7];
    const float* b_f          = (const float*)d_in[8];
    const float* Wi_b         = (const float*)d_in[9];
    const float* Wh_b         = (const float*)d_in[10];
    const float* b_b          = (const float*)d_in[11];
    const float* out_W        = (const float*)d_in[12];
    const float* out_b        = (const float*)d_in[13];
    const float* trans        = (const float*)d_in[14];
    const float* start_trans  = (const float*)d_in[15];
    const float* end_trans    = (const float*)d_in[16];
    float* out = (float*)d_out;

    const int SMEM_A = 32768 + 65536;                                       // 98304
    const int SMEM_S = 131072 + 8192 + 12288 + 1024;                        // 152576
    const int SMEM_P = (512 * 32 * 2 + 32 * 33 + 32) * (int)sizeof(float);  // 135424

    cudaFuncSetAttribute(wi_gemm_kernel, cudaFuncAttributeMaxDynamicSharedMemorySize, SMEM_A);
    cudaFuncSetAttribute(scan_kernel,    cudaFuncAttributeMaxDynamicSharedMemorySize, SMEM_S);
    cudaFuncSetAttribute(proj_kernel,    cudaFuncAttributeMaxDynamicSharedMemorySize, SMEM_P);

    init_kernel<<<2, 256>>>();

    dim3 ga(TT, 16);
    wi_gemm_kernel<<<ga, 256, SMEM_A>>>(chars, bigrams, char_table, bigram_table,
                                        Wi_f, b_f, Wi_b, b_b);

    scan_kernel<<<128, 128, SMEM_S>>>(Wh_f, Wh_b, seq_len);

    proj_kernel<<<TT, 256, SMEM_P>>>(out_W, out_b);

    crf_kernel<<<BB, 128>>>(seq_len, target, trans, start_trans, end_trans, out);
}